// round 9
// baseline (speedup 1.0000x reference)
#include <cuda_runtime.h>
#include <cuda_fp16.h>
#include <math.h>
#include <stdint.h>

// ---------------- problem constants ----------------
#define TT 256
#define BB 256
#define FF 128
#define HH 1024

// ---------------- tiling ----------------
#define KCH     64                         // K halves per chunk
#define ROWB    144                        // 72 halves per row
#define A_BYTES (64 * ROWB)                // 9216
#define W_BYTES (128 * ROWB)               // 18432
#define STAGE_BYTES (A_BYTES + W_BYTES)    // 27648
#define SMEM_BYTES  (4 * STAGE_BYTES)      // 110592

#define L1_NC    26                        // duo's L1 chunks (h1 cols [0,640))
#define TAIL_NC  6                         // spare chunks (h1 cols [640,1024))
#define TAIL_COL 640

// ---------------- persistent device state ----------------
__device__ __half g_h0h[2][BB * HH];
__device__ __half g_h1h[2][BB * HH];
__device__ __half g_xh[TT * BB * FF];
__device__ __half g_Wih0h[4 * HH * FF];
__device__ __half g_Whh0h[4 * HH * HH];
__device__ __half g_Wih1h[4 * HH * HH];
__device__ __half g_Whh1h[4 * HH * HH];
__device__ float  g_h0fin[BB * HH];
__device__ float  g_h1fin[BB * HH];
__device__ float  g_c0fin[BB * HH];
__device__ float  g_c1fin[BB * HH];
__device__ float  g_h1first[BB * HH];
__device__ float  g_part[128 * 64 * 128];   // per-duo L1 K-tail partial sums
__device__ uint32_t g_flag0[TT * 4];        // layer0 step done (per m group, 32 arrivals)
__device__ uint32_t g_flag1[TT * 4];        // layer1 step done
__device__ uint32_t g_flagp[TT * 128];      // spare partial ready (per duo, 1 arrival)

// ---------------- helpers ----------------
__device__ __forceinline__ uint32_t s2u(const void* p) {
    uint32_t a;
    asm("{ .reg .u64 t; cvta.to.shared.u64 t, %1; cvt.u32.u64 %0, t; }"
        : "=r"(a) : "l"(p));
    return a;
}

__device__ __forceinline__ void cp16(uint32_t s, const void* g) {
    asm volatile("cp.async.cg.shared.global [%0], [%1], 16;" :: "r"(s), "l"(g));
}
#define CP_COMMIT() asm volatile("cp.async.commit_group;" ::: "memory")
#define CP_WAIT(N)  asm volatile("cp.async.wait_group %0;" :: "n"(N) : "memory")

__device__ __forceinline__ void ldsm4(uint32_t* r, uint32_t addr) {
    asm volatile("ldmatrix.sync.aligned.m8n8.x4.shared.b16 {%0,%1,%2,%3}, [%4];"
        : "=r"(r[0]), "=r"(r[1]), "=r"(r[2]), "=r"(r[3]) : "r"(addr));
}

__device__ __forceinline__ void mma16(float* c, const uint32_t* a, uint32_t b0, uint32_t b1) {
    asm volatile(
        "mma.sync.aligned.m16n8k16.row.col.f32.f16.f16.f32 "
        "{%0,%1,%2,%3}, {%4,%5,%6,%7}, {%8,%9}, {%0,%1,%2,%3};"
        : "+f"(c[0]), "+f"(c[1]), "+f"(c[2]), "+f"(c[3])
        : "r"(a[0]), "r"(a[1]), "r"(a[2]), "r"(a[3]), "r"(b0), "r"(b1));
}

__device__ __forceinline__ void spin_ge(const uint32_t* p, uint32_t tgt) {
    uint32_t v;
    while (true) {
        asm volatile("ld.acquire.gpu.global.u32 %0, [%1];" : "=r"(v) : "l"(p) : "memory");
        if (v >= tgt) break;
        __nanosleep(32);
    }
}

__device__ __forceinline__ void rel_add(uint32_t* p) {
    asm volatile("red.release.gpu.global.add.u32 [%0], 1;" :: "l"(p) : "memory");
}

__device__ __forceinline__ float sigmoidf_(float x) { return 1.0f / (1.0f + expf(-x)); }

// ---------------- one-shot prep ----------------
#define N_X   (TT * BB * FF)
#define N_WI0 (4 * HH * FF)
#define N_WHH (4 * HH * HH)
#define N_Z   (BB * HH)
#define PREP_TOTAL (N_X + N_WI0 + 3 * N_WHH + 2 * N_Z + 2 * TT * 4 + TT * 128)

__global__ void prep_all(const float* __restrict__ x,
                         const float* __restrict__ wi0, const float* __restrict__ wh0,
                         const float* __restrict__ wi1, const float* __restrict__ wh1) {
    long long i = (long long)blockIdx.x * blockDim.x + threadIdx.x;
    if (i >= PREP_TOTAL) return;
    if (i < N_X) { g_xh[i] = __float2half_rn(x[i]); return; }
    i -= N_X;
    if (i < N_WI0) { g_Wih0h[i] = __float2half_rn(wi0[i]); return; }
    i -= N_WI0;
    if (i < N_WHH) { g_Whh0h[i] = __float2half_rn(wh0[i]); return; }
    i -= N_WHH;
    if (i < N_WHH) { g_Wih1h[i] = __float2half_rn(wi1[i]); return; }
    i -= N_WHH;
    if (i < N_WHH) { g_Whh1h[i] = __float2half_rn(wh1[i]); return; }
    i -= N_WHH;
    if (i < N_Z) { g_h0h[0][i] = __float2half(0.0f); return; }
    i -= N_Z;
    if (i < N_Z) { g_h1h[0][i] = __float2half(0.0f); return; }
    i -= N_Z;
    if (i < TT * 4) { g_flag0[i] = 0; return; }
    i -= TT * 4;
    if (i < TT * 4) { g_flag1[i] = 0; return; }
    i -= TT * 4;
    g_flagp[i] = 0;
}

// ---------------- chunk loaders (256 threads) ----------------
__device__ __forceinline__ void loadA(uint32_t dstA, int tid,
                                      const __half* __restrict__ aSrc, int ald) {
#pragma unroll
    for (int i = 0; i < 2; i++) {            // 64 rows x 8 segs
        int q = tid + i * 256;
        int row = q >> 3, seg = q & 7;
        cp16(dstA + row * ROWB + seg * 16, aSrc + (size_t)row * ald + seg * 8);
    }
}

__device__ __forceinline__ void loadW(uint32_t dstW, int tid,
                                      const __half* __restrict__ wSrc, int wld, int j0) {
#pragma unroll
    for (int i = 0; i < 4; i++) {            // 128 rows x 8 segs
        int q = tid + i * 256;
        int row = q >> 3, seg = q & 7;
        int g = row >> 5, u = row & 31;
        cp16(dstW + row * ROWB + seg * 16,
             wSrc + (size_t)(g * HH + j0 + u) * wld + seg * 8);
    }
}

// ---------------- generic pipelined GEMM phase ----------------
// Tile: M=64 (b0..b0+64), N=128 (4 gates x 32 units at j0), K = NC*64 halves.
// Chunks [0,SPLIT) use inP/Wih (ld = wihLd); chunks [SPLIT,NC) use hP/Whh (ld = HH).
// preA: spun once before first A load. hgate: spun just before chunk SPLIT's A load.
template <int NC, int SPLIT>
__device__ __forceinline__ void gemm_phase(
    uint32_t smb, int tid, int j0, int b0,
    uint32_t aoff0, uint32_t aoff1, uint32_t boffA, uint32_t boffB,
    const __half* __restrict__ inP, const __half* __restrict__ hP,
    const __half* __restrict__ Wih, const __half* __restrict__ Whh, int wihLd,
    const uint32_t* preA, uint32_t preATgt,
    const uint32_t* hgate, uint32_t hgateTgt,
    float acc[2][4][4])
{
    auto wsrc_for = [&](int ch, const __half*& ws, int& wld) {
        if (ch < SPLIT) { ws = Wih + ch * KCH; wld = wihLd; }
        else            { ws = Whh + (ch - SPLIT) * KCH; wld = HH; }
    };
    auto asrc_for = [&](int ch, const __half*& as, int& ald) {
        if (ch < SPLIT) { as = inP + (size_t)b0 * wihLd + ch * KCH; ald = wihLd; }
        else            { as = hP + (size_t)b0 * HH + (ch - SPLIT) * KCH; ald = HH; }
    };

    // prologue: weights first (flag-independent), then gated A loads
#pragma unroll
    for (int st = 0; st < 3; st++) {
        const __half* ws; int wld;
        wsrc_for(st, ws, wld);
        loadW(smb + st * STAGE_BYTES + A_BYTES, tid, ws, wld, j0);
    }
    if (preA) { if (tid == 0) spin_ge(preA, preATgt); __syncthreads(); }
#pragma unroll
    for (int st = 0; st < 3; st++) {
        if (st == SPLIT && hgate) {
            if (tid == 0) spin_ge(hgate, hgateTgt);
            __syncthreads();
        }
        const __half* as; int ald;
        asrc_for(st, as, ald);
        loadA(smb + st * STAGE_BYTES, tid, as, ald);
        CP_COMMIT();
    }

#pragma unroll
    for (int mi = 0; mi < 2; mi++)
#pragma unroll
        for (int g = 0; g < 4; g++)
#pragma unroll
            for (int q = 0; q < 4; q++) acc[mi][g][q] = 0.0f;

#pragma unroll 1
    for (int ch = 0; ch < NC; ch++) {
        if (ch >= NC - 1)      { CP_WAIT(0); }
        else if (ch == NC - 2) { CP_WAIT(1); }
        else                   { CP_WAIT(2); }
        __syncthreads();

        if (ch + 3 < NC) {
            int buf = (ch + 3) & 3;
            const __half* ws; int wld;
            wsrc_for(ch + 3, ws, wld);
            loadW(smb + buf * STAGE_BYTES + A_BYTES, tid, ws, wld, j0);
            if (ch + 3 == SPLIT && hgate) {
                if (tid == 0) spin_ge(hgate, hgateTgt);
                __syncthreads();
            }
            const __half* as; int ald;
            asrc_for(ch + 3, as, ald);
            loadA(smb + buf * STAGE_BYTES, tid, as, ald);
            CP_COMMIT();
        }

        const uint32_t aBase = smb + (ch & 3) * STAGE_BYTES;
        const uint32_t wBase = aBase + A_BYTES;

#pragma unroll
        for (int ks = 0; ks < 4; ks++) {
            uint32_t a0[4], a1[4], bA[4], bB[4];
            ldsm4(a0, aBase + aoff0 + ks * 32);
            ldsm4(a1, aBase + aoff1 + ks * 32);
            ldsm4(bA, wBase + boffA + ks * 32);
            ldsm4(bB, wBase + boffB + ks * 32);
            mma16(acc[0][0], a0, bA[0], bA[1]);
            mma16(acc[1][0], a1, bA[0], bA[1]);
            mma16(acc[0][1], a0, bA[2], bA[3]);
            mma16(acc[1][1], a1, bA[2], bA[3]);
            mma16(acc[0][2], a0, bB[0], bB[1]);
            mma16(acc[1][2], a1, bB[0], bB[1]);
            mma16(acc[0][3], a0, bB[2], bB[3]);
            mme_dummy:;
            mma16(acc[1][3], a1, bB[2], bB[3]);
        }
    }
}

// ---------------- duo CTA: layer0 tile + layer1 tile (K-split, spare-assisted) ----------------
__device__ void duo_run(int bid, char* smraw, float* bias0_s, float* bias1_s,
                        const float* __restrict__ bih0, const float* __restrict__ bhh0,
                        const float* __restrict__ bih1, const float* __restrict__ bhh1) {
    const int tid  = threadIdx.x;
    const int w    = tid >> 5;
    const int lane = tid & 31;
    const int wm   = w & 1;
    const int wn   = w >> 1;
    const int r4   = lane >> 2, cl = lane & 3;
    const int m    = bid & 3;
    const int nt   = bid >> 2;
    const int b0   = m * 64;
    const int j0   = nt * 32;

    const uint32_t smb = s2u(smraw);

    if (tid < 128) {
        int g = tid >> 5, u = tid & 31;
        bias0_s[tid] = bih0[g * HH + j0 + u] + bhh0[g * HH + j0 + u];
        bias1_s[tid] = bih1[g * HH + j0 + u] + bhh1[g * HH + j0 + u];
    }
    __syncthreads();

    const int arow = (lane & 7) + ((lane >> 3) & 1) * 8;
    const int aseg = (lane >> 4) & 1;
    const uint32_t aoff0 = (uint32_t)((wm * 32 + arow) * ROWB + aseg * 16);
    const uint32_t aoff1 = (uint32_t)((wm * 32 + 16 + arow) * ROWB + aseg * 16);
    const uint32_t boffA = (uint32_t)((((lane >> 4) & 1) * 32 + wn * 8 + (lane & 7)) * ROWB
                                      + ((lane >> 3) & 1) * 16);
    const uint32_t boffB = boffA + 64u * ROWB;

    float c0[2][2][2], c1[2][2][2];
#pragma unroll
    for (int a = 0; a < 2; a++)
#pragma unroll
        for (int b = 0; b < 2; b++)
#pragma unroll
            for (int d = 0; d < 2; d++) { c0[a][b][d] = 0.0f; c1[a][b][d] = 0.0f; }

    float acc[2][4][4];

#pragma unroll 1
    for (int s = 0; s < TT; s++) {
        // ================= layer 0, step s =================
        gemm_phase<18, 2>(smb, tid, j0, b0, aoff0, aoff1, boffA, boffB,
                          g_xh + (size_t)s * BB * FF, g_h0h[s & 1],
                          g_Wih0h, g_Whh0h, FF,
                          nullptr, 0,
                          (s > 0) ? &g_flag0[(s - 1) * 4 + m] : nullptr, 32,
                          acc);
        {
            __half* hOut = g_h0h[(s + 1) & 1];
#pragma unroll
            for (int mi = 0; mi < 2; mi++)
#pragma unroll
                for (int rh = 0; rh < 2; rh++) {
                    const int row = b0 + wm * 32 + mi * 16 + r4 + rh * 8;
                    const int col = j0 + wn * 8 + 2 * cl;
                    float hv[2];
#pragma unroll
                    for (int du = 0; du < 2; du++) {
                        const int q = rh * 2 + du;
                        const int ul = wn * 8 + 2 * cl + du;
                        float iv = acc[mi][0][q] + bias0_s[ul];
                        float fv = acc[mi][1][q] + bias0_s[32 + ul];
                        float gv = acc[mi][2][q] + bias0_s[64 + ul];
                        float ov = acc[mi][3][q] + bias0_s[96 + ul];
                        float cn = sigmoidf_(fv) * c0[mi][rh][du]
                                 + sigmoidf_(iv) * tanhf(gv);
                        c0[mi][rh][du] = cn;
                        hv[du] = sigmoidf_(ov) * tanhf(cn);
                    }
                    *(__half2*)&hOut[(size_t)row * HH + col] =
                        __floats2half2_rn(hv[0], hv[1]);
                    if (s == TT - 1) {
                        *(float2*)&g_h0fin[(size_t)row * HH + col] = make_float2(hv[0], hv[1]);
                        *(float2*)&g_c0fin[(size_t)row * HH + col] =
                            make_float2(c0[mi][rh][0], c0[mi][rh][1]);
                    }
                }
        }
        __syncthreads();
        if (tid == 0) rel_add(&g_flag0[s * 4 + m]);

        // ================= layer 1, step s (chunks 0..25; tail from spare) =================
        gemm_phase<L1_NC, 16>(smb, tid, j0, b0, aoff0, aoff1, boffA, boffB,
                              g_h0h[(s + 1) & 1], g_h1h[s & 1],
                              g_Wih1h, g_Whh1h, HH,
                              &g_flag0[s * 4 + m], 32,
                              (s > 0) ? &g_flag1[(s - 1) * 4 + m] : nullptr, 32,
                              acc);
        // add spare's K-tail partial
        if (tid == 0) spin_ge(&g_flagp[s * 128 + bid], 1);
        __syncthreads();
        {
            const float4* pp = (const float4*)(g_part + (size_t)bid * 8192) + tid * 8;
            float* af = &acc[0][0][0];
#pragma unroll
            for (int i = 0; i < 8; i++) {
                float4 v = pp[i];
                af[4 * i + 0] += v.x; af[4 * i + 1] += v.y;
                af[4 * i + 2] += v.z; af[4 * i + 3] += v.w;
            }
        }
        {
            __half* hOut = g_h1h[(s + 1) & 1];
#pragma unroll
            for (int mi = 0; mi < 2; mi++)
#pragma unroll
                for (int rh = 0; rh < 2; rh++) {
                    const int row = b0 + wm * 32 + mi * 16 + r4 + rh * 8;
                    const int col = j0 + wn * 8 + 2 * cl;
                    float hv[2];
#pragma unroll
                    for (int du = 0; du < 2; du++) {
                        const int q = rh * 2 + du;
                        const int ul = wn * 8 + 2 * cl + du;
                        float iv = acc[mi][0][q] + bias1_s[ul];
                        float fv = acc[mi][1][q] + bias1_s[32 + ul];
                        float gv = acc[mi][2][q] + bias1_s[64 + ul];
                        float ov = acc[mi][3][q] + bias1_s[96 + ul];
                        float cn = sigmoidf_(fv) * c1[mi][rh][du]
                                 + sigmoidf_(iv) * tanhf(gv);
                        c1[mi][rh][du] = cn;
                        hv[du] = sigmoidf_(ov) * tanhf(cn);
                    }
                    *(__half2*)&hOut[(size_t)row * HH + col] =
                        __floats2half2_rn(hv[0], hv[1]);
                    if (s == 0)
                        *(float2*)&g_h1first[(size_t)row * HH + col] =
                            make_float2(hv[0], hv[1]);
                    if (s == TT - 1) {
                        *(float2*)&g_h1fin[(size_t)row * HH + col] =
                            make_float2(hv[0], hv[1]);
                        *(float2*)&g_c1fin[(size_t)row * HH + col] =
                            make_float2(c1[mi][rh][0], c1[mi][rh][1]);
                    }
                }
        }
        __syncthreads();
        if (tid == 0) rel_add(&g_flag1[s * 4 + m]);
    }
}

// ---------------- spare CTA: layer1 K-tail partials for 6-7 duos ----------------
__device__ void spare_run(int j, char* smraw) {
    const int tid  = threadIdx.x;
    const int w    = tid >> 5;
    const int lane = tid & 31;
    const int wm   = w & 1;
    const int wn   = w >> 1;
    const uint32_t smb = s2u(smraw);

    const int arow = (lane & 7) + ((lane >> 3) & 1) * 8;
    const int aseg = (lane >> 4) & 1;
    const uint32_t aoff0 = (uint32_t)((wm * 32 + arow) * ROWB + aseg * 16);
    const uint32_t aoff1 = (uint32_t)((wm * 32 + 16 + arow) * ROWB + aseg * 16);
    const uint32_t boffA = (uint32_t)((((lane >> 4) & 1) * 32 + wn * 8 + (lane & 7)) * ROWB
                                      + ((lane >> 3) & 1) * 16);
    const uint32_t boffB = boffA + 64u * ROWB;

    const int d0  = (j < 8) ? j * 7 : 56 + (j - 8) * 6;
    const int cnt = (j < 8) ? 7 : 6;

    float acc[2][4][4];

#pragma unroll 1
    for (int s = 0; s < TT; s++) {
        if (s > 0) {
            if (tid == 0) {
#pragma unroll
                for (int mm = 0; mm < 4; mm++) spin_ge(&g_flag1[(s - 1) * 4 + mm], 32);
            }
            __syncthreads();
        }
        const __half* hP = g_h1h[s & 1] + TAIL_COL;

#pragma unroll 1
        for (int k = 0; k < cnt; k++) {
            const int d  = d0 + k;
            const int b0 = (d & 3) * 64;
            const int j0 = (d >> 2) * 32;
            gemm_phase<TAIL_NC, 0>(smb, tid, j0, b0, aoff0, aoff1, boffA, boffB,
                                   hP, hP,
                                   g_Whh1h + TAIL_COL, g_Whh1h + TAIL_COL, HH,
                                   nullptr, 0, nullptr, 0, acc);
            {
                float4* pp = (float4*)(g_part + (size_t)d * 8192) + tid * 8;
                const float* af = &acc[0][0][0];
#pragma unroll
                for (int i = 0; i < 8; i++)
                    pp[i] = make_float4(af[4 * i], af[4 * i + 1],
                                        af[4 * i + 2], af[4 * i + 3]);
            }
            __syncthreads();
            if (tid == 0) rel_add(&g_flagp[s * 128 + d]);
        }
    }
}

__global__ __launch_bounds__(256, 1) void lstm_persistent(
    const float* __restrict__ bih0, const float* __restrict__ bhh0,
    const float* __restrict__ bih1, const float* __restrict__ bhh1) {
    extern __shared__ char smraw[];
    __shared__ float bias0_s[128];
    __shared__ float bias1_s[128];
    if (blockIdx.x < 128)
        duo_run(blockIdx.x, smraw, bias0_s, bias1_s, bih0, bhh0, bih1, bhh1);
    else
        spare_run(blockIdx.x - 128, smraw);
}

// ---------------- head + output packing ----------------
__global__ void linear_kernel(const float* __restrict__ W_lin,
                              const float* __restrict__ b_lin,
                              float* __restrict__ y) {
    __shared__ float hrow[HH];
    const int b = blockIdx.x;
    for (int i = threadIdx.x; i < HH; i += blockDim.x)
        hrow[i] = g_h1first[(size_t)b * HH + i];
    __syncthreads();
    const int f = threadIdx.x;
    float acc = b_lin[f];
    const float* wv = &W_lin[(size_t)f * HH];
#pragma unroll 4
    for (int k = 0; k < HH; k++) acc += hrow[k] * wv[k];
    y[(size_t)b * FF + f] = acc;
}

__global__ void write_states_kernel(float* __restrict__ out) {
    int i = blockIdx.x * blockDim.x + threadIdx.x;
    if (i >= BB * HH) return;
    const int YO = BB * FF;
    out[YO + i]               = g_h0fin[i];
    out[YO + BB * HH + i]     = g_h1fin[i];
    out[YO + 2 * BB * HH + i] = g_c0fin[i];
    out[YO + 3 * BB * HH + i] = g_c1fin[i];
}

extern "C" void kernel_launch(void* const* d_in, const int* in_sizes, int n_in,
                              void* d_out, int out_size) {
    (void)in_sizes; (void)n_in; (void)out_size;
    const float* x     = (const float*)d_in[0];
    const float* W_ih0 = (const float*)d_in[1];
    const float* W_hh0 = (const float*)d_in[2];
    const float* b_ih0 = (const float*)d_in[3];
    const float* b_hh0 = (const float*)d_in[4];
    const float* W_ih1 = (const float*)d_in[5];
    const float* W_hh1 = (const float*)d_in[6];
    const float* b_ih1 = (const float*)d_in[7];
    const float* b_hh1 = (const float*)d_in[8];
    const float* W_lin = (const float*)d_in[9];
    const float* b_lin = (const float*)d_in[10];
    float* out = (float*)d_out;

    cudaFuncSetAttribute(lstm_persistent,
                         cudaFuncAttributeMaxDynamicSharedMemorySize, SMEM_BYTES);

    prep_all<<<(PREP_TOTAL + 255) / 256, 256>>>(x, W_ih0, W_hh0, W_ih1, W_hh1);
    lstm_persistent<<<148, 256, SMEM_BYTES>>>(b_ih0, b_hh0, b_ih1, b_hh1);
    linear_kernel<<<BB, FF>>>(W_lin, b_lin, out);
    write_states_kernel<<<(BB * HH + 255) / 256, 256>>>(out);
}

// round 10
// speedup vs baseline: 1.1521x; 1.1521x over previous
#include <cuda_runtime.h>
#include <cuda_fp16.h>
#include <math.h>
#include <stdint.h>

// ---------------- problem constants ----------------
#define TT 256
#define BB 256
#define FF 128
#define HH 1024

// ---------------- tiling ----------------
#define KCH     64                         // K halves per chunk
#define ROWB    144                        // 72 halves per row
#define A_BYTES (64 * ROWB)                // 9216
#define W_BYTES (128 * ROWB)               // 18432
#define STAGE_BYTES (A_BYTES + W_BYTES)    // 27648
#define SMEM_BYTES  (4 * STAGE_BYTES)      // 110592

#define TAILC   4                          // L1 K-chunks offloaded to helpers
#define TAIL_K  (HH - TAILC * KCH)         // h1 col offset 768

// ---------------- persistent device state ----------------
__device__ __half g_h0h[3][BB * HH];       // triple-buffered h0
__device__ __half g_h1h[2][BB * HH];
__device__ __half g_xh[TT * BB * FF];
__device__ __half g_Wih0h[4 * HH * FF];
__device__ __half g_Whh0h[4 * HH * HH];
__device__ __half g_Wih1h[4 * HH * HH];
__device__ __half g_Whh1h[4 * HH * HH];
__device__ float  g_h0fin[BB * HH];
__device__ float  g_h1fin[BB * HH];
__device__ float  g_c0fin[BB * HH];
__device__ float  g_c1fin[BB * HH];
__device__ float  g_h1first[BB * HH];
__device__ float  g_part[128 * 64 * 128];  // per-L1-tile K-tail partials (32 f32/thread)
__device__ uint32_t g_flag0[TT * 4];       // layer0 step done (per m group)
__device__ uint32_t g_flag1[TT * 4];       // layer1 step done
__device__ uint32_t g_cons[TT * 4];        // layer1 consumed h0(s+1)
__device__ uint32_t g_flagp[TT * 128];     // helper partial ready (per L1 tile)

// ---------------- helpers ----------------
__device__ __forceinline__ uint32_t s2u(const void* p) {
    uint32_t a;
    asm("{ .reg .u64 t; cvta.to.shared.u64 t, %1; cvt.u32.u64 %0, t; }"
        : "=r"(a) : "l"(p));
    return a;
}

__device__ __forceinline__ void cp16(uint32_t s, const void* g) {
    asm volatile("cp.async.cg.shared.global [%0], [%1], 16;" :: "r"(s), "l"(g));
}
#define CP_COMMIT() asm volatile("cp.async.commit_group;" ::: "memory")
#define CP_WAIT(N)  asm volatile("cp.async.wait_group %0;" :: "n"(N) : "memory")

__device__ __forceinline__ void ldsm4(uint32_t* r, uint32_t addr) {
    asm volatile("ldmatrix.sync.aligned.m8n8.x4.shared.b16 {%0,%1,%2,%3}, [%4];"
        : "=r"(r[0]), "=r"(r[1]), "=r"(r[2]), "=r"(r[3]) : "r"(addr));
}

__device__ __forceinline__ void mma16(float* c, const uint32_t* a, uint32_t b0, uint32_t b1) {
    asm volatile(
        "mma.sync.aligned.m16n8k16.row.col.f32.f16.f16.f32 "
        "{%0,%1,%2,%3}, {%4,%5,%6,%7}, {%8,%9}, {%0,%1,%2,%3};"
        : "+f"(c[0]), "+f"(c[1]), "+f"(c[2]), "+f"(c[3])
        : "r"(a[0]), "r"(a[1]), "r"(a[2]), "r"(a[3]), "r"(b0), "r"(b1));
}

__device__ __forceinline__ void spin_ge(const uint32_t* p, uint32_t tgt) {
    uint32_t v;
    while (true) {
        asm volatile("ld.acquire.gpu.global.u32 %0, [%1];" : "=r"(v) : "l"(p) : "memory");
        if (v >= tgt) break;
        __nanosleep(32);
    }
}

__device__ __forceinline__ void rel_add(uint32_t* p) {
    asm volatile("red.release.gpu.global.add.u32 [%0], 1;" :: "l"(p) : "memory");
}

__device__ __forceinline__ float sigmoidf_(float x) { return 1.0f / (1.0f + expf(-x)); }

// ---------------- one-shot prep: fp16 conversions + state/flag zeroing ----------------
#define N_X   (TT * BB * FF)
#define N_WI0 (4 * HH * FF)
#define N_WHH (4 * HH * HH)
#define N_Z   (BB * HH)
#define PREP_TOTAL (N_X + N_WI0 + 3 * N_WHH + 2 * N_Z + 3 * TT * 4 + TT * 128)

__global__ void prep_all(const float* __restrict__ x,
                         const float* __restrict__ wi0, const float* __restrict__ wh0,
                         const float* __restrict__ wi1, const float* __restrict__ wh1) {
    long long i = (long long)blockIdx.x * blockDim.x + threadIdx.x;
    if (i >= PREP_TOTAL) return;
    if (i < N_X) { g_xh[i] = __float2half_rn(x[i]); return; }
    i -= N_X;
    if (i < N_WI0) { g_Wih0h[i] = __float2half_rn(wi0[i]); return; }
    i -= N_WI0;
    if (i < N_WHH) { g_Whh0h[i] = __float2half_rn(wh0[i]); return; }
    i -= N_WHH;
    if (i < N_WHH) { g_Wih1h[i] = __float2half_rn(wi1[i]); return; }
    i -= N_WHH;
    if (i < N_WHH) { g_Whh1h[i] = __float2half_rn(wh1[i]); return; }
    i -= N_WHH;
    if (i < N_Z) { g_h0h[0][i] = __float2half(0.0f); return; }
    i -= N_Z;
    if (i < N_Z) { g_h1h[0][i] = __float2half(0.0f); return; }
    i -= N_Z;
    if (i < TT * 4) { g_flag0[i] = 0; return; }
    i -= TT * 4;
    if (i < TT * 4) { g_flag1[i] = 0; return; }
    i -= TT * 4;
    if (i < TT * 4) { g_cons[i] = 0; return; }
    i -= TT * 4;
    g_flagp[i] = 0;
}

// ---------------- split chunk loaders (256 threads) ----------------
__device__ __forceinline__ void loadA(uint32_t dstA, int tid,
                                      const __half* __restrict__ aSrc, int ald) {
#pragma unroll
    for (int i = 0; i < 2; i++) {            // 64 rows x 8 segs
        int q = tid + i * 256;
        int row = q >> 3, seg = q & 7;
        cp16(dstA + row * ROWB + seg * 16, aSrc + (size_t)row * ald + seg * 8);
    }
}

__device__ __forceinline__ void loadW(uint32_t dstW, int tid,
                                      const __half* __restrict__ wSrc, int wld, int j0) {
#pragma unroll
    for (int i = 0; i < 4; i++) {            // 128 rows x 8 segs
        int q = tid + i * 256;
        int row = q >> 3, seg = q & 7;
        int g = row >> 5, u = row & 31;
        cp16(dstW + row * ROWB + seg * 16,
             wSrc + (size_t)(g * HH + j0 + u) * wld + seg * 8);
    }
}

// ---------------- persistent LSTM CTA (R8 structure + L1 K-tail offload) ----------------
template <int K_IN, int LAYER>
__device__ __forceinline__ void lstm_run(int bid, char* smraw, float* bias_s,
                                         const float* __restrict__ b_ih,
                                         const float* __restrict__ b_hh) {
    constexpr int NC    = (K_IN + HH) / KCH;
    constexpr int SPLIT = K_IN / KCH;
    constexpr int NCE   = LAYER ? (NC - TAILC) : NC;   // L1: 28, L0: 18

    const int tid  = threadIdx.x;
    const int w    = tid >> 5;
    const int lane = tid & 31;
    const int wm   = w & 1;
    const int wn   = w >> 1;
    const int r4   = lane >> 2, cl = lane & 3;
    const int m    = bid & 3;
    const int nt   = bid >> 2;
    const int b0   = m * 64;
    const int j0   = nt * 32;

    const uint32_t smb = s2u(smraw);
    const __half* Wih = LAYER ? g_Wih1h : g_Wih0h;
    const __half* Whh = LAYER ? g_Whh1h : g_Whh0h;

    if (tid < 128) {
        int g = tid >> 5, u = tid & 31;
        bias_s[tid] = b_ih[g * HH + j0 + u] + b_hh[g * HH + j0 + u];
    }
    __syncthreads();

    const int arow = (lane & 7) + ((lane >> 3) & 1) * 8;
    const int aseg = (lane >> 4) & 1;
    const uint32_t aoff0 = (uint32_t)((wm * 32 + arow) * ROWB + aseg * 16);
    const uint32_t aoff1 = (uint32_t)((wm * 32 + 16 + arow) * ROWB + aseg * 16);
    const uint32_t boffA = (uint32_t)((((lane >> 4) & 1) * 32 + wn * 8 + (lane & 7)) * ROWB
                                      + ((lane >> 3) & 1) * 16);
    const uint32_t boffB = boffA + 64u * ROWB;

    float c_reg[2][2][2];
#pragma unroll
    for (int a = 0; a < 2; a++)
#pragma unroll
        for (int b = 0; b < 2; b++)
#pragma unroll
            for (int d = 0; d < 2; d++) c_reg[a][b][d] = 0.0f;

#pragma unroll 1
    for (int s = 0; s < TT; s++) {
        const __half* inP = LAYER ? g_h0h[(s + 1) % 3]
                                  : g_xh + (size_t)s * BB * FF;
        const __half* hP  = LAYER ? g_h1h[s & 1] : g_h0h[s % 3];

        auto wsrc_for = [&](int ch, const __half*& ws, int& wld) {
            if (ch < SPLIT) { ws = Wih + ch * KCH; wld = K_IN; }
            else            { ws = Whh + (ch - SPLIT) * KCH; wld = HH; }
        };
        auto asrc_for = [&](int ch, const __half*& as, int& ald) {
            if (ch < SPLIT) { as = inP + (size_t)b0 * K_IN + ch * KCH; ald = K_IN; }
            else            { as = hP + (size_t)b0 * HH + (ch - SPLIT) * KCH; ald = HH; }
        };

        // ---- prologue: flag-independent W (and x) loads BEFORE spins ----
#pragma unroll
        for (int st = 0; st < 3; st++) {
            const __half* ws; int wld;
            wsrc_for(st, ws, wld);
            loadW(smb + st * STAGE_BYTES + A_BYTES, tid, ws, wld, j0);
        }

        if (LAYER == 0) {
            const __half* as; int ald;
            asrc_for(0, as, ald);
            loadA(smb + 0 * STAGE_BYTES, tid, as, ald);
            CP_COMMIT();
            asrc_for(1, as, ald);
            loadA(smb + 1 * STAGE_BYTES, tid, as, ald);
            CP_COMMIT();
            if (s > 0) {
                if (tid == 0) spin_ge(&g_flag0[(s - 1) * 4 + m], 32);
                __syncthreads();
            }
            asrc_for(2, as, ald);
            loadA(smb + 2 * STAGE_BYTES, tid, as, ald);
            CP_COMMIT();
        } else {
            if (tid == 0) spin_ge(&g_flag0[s * 4 + m], 32);
            __syncthreads();
#pragma unroll
            for (int st = 0; st < 3; st++) {
                const __half* as; int ald;
                asrc_for(st, as, ald);
                loadA(smb + st * STAGE_BYTES, tid, as, ald);
                CP_COMMIT();
            }
        }

        float acc[2][4][4];
#pragma unroll
        for (int mi = 0; mi < 2; mi++)
#pragma unroll
            for (int g = 0; g < 4; g++)
#pragma unroll
                for (int q = 0; q < 4; q++) acc[mi][g][q] = 0.0f;

#pragma unroll 1
        for (int ch = 0; ch < NCE; ch++) {
            if (ch >= NCE - 1)      { CP_WAIT(0); }
            else if (ch == NCE - 2) { CP_WAIT(1); }
            else                    { CP_WAIT(2); }
            __syncthreads();

            if (ch + 3 < NCE) {
                int buf = (ch + 3) & 3;
                const __half* ws; int wld;
                wsrc_for(ch + 3, ws, wld);
                loadW(smb + buf * STAGE_BYTES + A_BYTES, tid, ws, wld, j0);

                if (LAYER == 1 && s > 0 && ch == SPLIT - 3) {
                    if (tid == 0) spin_ge(&g_flag1[(s - 1) * 4 + m], 32);
                    __syncthreads();
                }

                const __half* as; int ald;
                asrc_for(ch + 3, as, ald);
                loadA(smb + buf * STAGE_BYTES, tid, as, ald);
                CP_COMMIT();
            }

            const uint32_t aBase = smb + (ch & 3) * STAGE_BYTES;
            const uint32_t wBase = aBase + A_BYTES;

#pragma unroll
            for (int ks = 0; ks < 4; ks++) {
                uint32_t a0[4], a1[4], bA[4], bB[4];
                ldsm4(a0, aBase + aoff0 + ks * 32);
                ldsm4(a1, aBase + aoff1 + ks * 32);
                ldsm4(bA, wBase + boffA + ks * 32);
                ldsm4(bB, wBase + boffB + ks * 32);
                mma16(acc[0][0], a0, bA[0], bA[1]);
                mma16(acc[1][0], a1, bA[0], bA[1]);
                mma16(acc[0][1], a0, bA[2], bA[3]);
                mma16(acc[1][1], a1, bA[2], bA[3]);
                mma16(acc[0][2], a0, bB[0], bB[1]);
                mma16(acc[1][2], a1, bB[0], bB[1]);
                mma16(acc[0][3], a0, bB[2], bB[3]);
                mma16(acc[1][3], a1, bB[2], bB[3]);
            }
        }

        __syncthreads();
        // layer1: signal h0(s+1) fully consumed
        if (LAYER == 1 && tid == 0) rel_add(&g_cons[s * 4 + m]);

        // layer1: fold in the helper's K-tail partial before the gate math
        if (LAYER == 1) {
            if (tid == 0) spin_ge(&g_flagp[s * 128 + bid], 1);
            __syncthreads();
            const float4* pp = (const float4*)(g_part + (size_t)bid * 8192) + tid * 8;
            float* af = &acc[0][0][0];
#pragma unroll
            for (int i = 0; i < 8; i++) {
                float4 v = pp[i];
                af[4 * i + 0] += v.x; af[4 * i + 1] += v.y;
                af[4 * i + 2] += v.z; af[4 * i + 3] += v.w;
            }
        }

        // ---- epilogue: compute gates first (before any WAR spin) ----
        float hv_all[2][2][2];
#pragma unroll
        for (int mi = 0; mi < 2; mi++)
#pragma unroll
            for (int rh = 0; rh < 2; rh++)
#pragma unroll
                for (int du = 0; du < 2; du++) {
                    const int q = rh * 2 + du;
                    const int ul = wn * 8 + 2 * cl + du;
                    float iv = acc[mi][0][q] + bias_s[ul];
                    float fv = acc[mi][1][q] + bias_s[32 + ul];
                    float gv = acc[mi][2][q] + bias_s[64 + ul];
                    float ov = acc[mi][3][q] + bias_s[96 + ul];
                    float cn = sigmoidf_(fv) * c_reg[mi][rh][du]
                             + sigmoidf_(iv) * tanhf(gv);
                    c_reg[mi][rh][du] = cn;
                    hv_all[mi][rh][du] = sigmoidf_(ov) * tanhf(cn);
                }

        // layer0 WAR: before overwriting h0 slot (s+1)%3, wait for cons(s-3)
        if (LAYER == 0 && s >= 3) {
            if (tid == 0) spin_ge(&g_cons[(s - 3) * 4 + m], 32);
            __syncthreads();
        }

        __half* hOut = LAYER ? g_h1h[(s + 1) & 1] : g_h0h[(s + 1) % 3];
#pragma unroll
        for (int mi = 0; mi < 2; mi++)
#pragma unroll
            for (int rh = 0; rh < 2; rh++) {
                const int row = b0 + wm * 32 + mi * 16 + r4 + rh * 8;
                const int col = j0 + wn * 8 + 2 * cl;
                *(__half2*)&hOut[(size_t)row * HH + col] =
                    __floats2half2_rn(hv_all[mi][rh][0], hv_all[mi][rh][1]);
                if (LAYER == 1 && s == 0)
                    *(float2*)&g_h1first[(size_t)row * HH + col] =
                        make_float2(hv_all[mi][rh][0], hv_all[mi][rh][1]);
                if (s == TT - 1) {
                    float* hf = LAYER ? g_h1fin : g_h0fin;
                    float* cf = LAYER ? g_c1fin : g_c0fin;
                    *(float2*)&hf[(size_t)row * HH + col] =
                        make_float2(hv_all[mi][rh][0], hv_all[mi][rh][1]);
                    *(float2*)&cf[(size_t)row * HH + col] =
                        make_float2(c_reg[mi][rh][0], c_reg[mi][rh][1]);
                }
            }
        __syncthreads();
        if (tid == 0) rel_add(LAYER ? &g_flag1[s * 4 + m] : &g_flag0[s * 4 + m]);
    }
}

// ---------------- helper CTA: L1 K-tail partials (h1 cols [768,1024)) ----------------
__device__ void helper_run(int j, char* smraw) {
    const int tid  = threadIdx.x;
    const int w    = tid >> 5;
    const int lane = tid & 31;
    const int wm   = w & 1;
    const int wn   = w >> 1;
    const uint32_t smb = s2u(smraw);

    const int arow = (lane & 7) + ((lane >> 3) & 1) * 8;
    const int aseg = (lane >> 4) & 1;
    const uint32_t aoff0 = (uint32_t)((wm * 32 + arow) * ROWB + aseg * 16);
    const uint32_t aoff1 = (uint32_t)((wm * 32 + 16 + arow) * ROWB + aseg * 16);
    const uint32_t boffA = (uint32_t)((((lane >> 4) & 1) * 32 + wn * 8 + (lane & 7)) * ROWB
                                      + ((lane >> 3) & 1) * 16);
    const uint32_t boffB = boffA + 64u * ROWB;

    const int d0  = (j < 8) ? j * 7 : 56 + (j - 8) * 6;
    const int cnt = (j < 8) ? 7 : 6;

#pragma unroll 1
    for (int s = 0; s < TT; s++) {
        if (s > 0) {
            if (tid == 0) {
#pragma unroll
                for (int mm = 0; mm < 4; mm++) spin_ge(&g_flag1[(s - 1) * 4 + mm], 32);
            }
            __syncthreads();
        }
        const __half* hB = g_h1h[s & 1];

#pragma unroll 1
        for (int k = 0; k < cnt; k++) {
            const int d  = d0 + k;
            const int b0 = (d & 3) * 64;
            const int j0 = (d >> 2) * 32;

            // prologue: 3 of 4 chunks
#pragma unroll
            for (int st = 0; st < 3; st++) {
                loadW(smb + st * STAGE_BYTES + A_BYTES, tid,
                      g_Whh1h + TAIL_K + st * KCH, HH, j0);
                loadA(smb + st * STAGE_BYTES, tid,
                      hB + (size_t)b0 * HH + TAIL_K + st * KCH, HH);
                CP_COMMIT();
            }

            float acc[2][4][4];
#pragma unroll
            for (int mi = 0; mi < 2; mi++)
#pragma unroll
                for (int g = 0; g < 4; g++)
#pragma unroll
                    for (int q = 0; q < 4; q++) acc[mi][g][q] = 0.0f;

#pragma unroll 1
            for (int ch = 0; ch < TAILC; ch++) {
                if (ch >= TAILC - 1)      { CP_WAIT(0); }
                else if (ch == TAILC - 2) { CP_WAIT(1); }
                else                      { CP_WAIT(2); }
                __syncthreads();

                if (ch == 0) {
                    loadW(smb + 3 * STAGE_BYTES + A_BYTES, tid,
                          g_Whh1h + TAIL_K + 3 * KCH, HH, j0);
                    loadA(smb + 3 * STAGE_BYTES, tid,
                          hB + (size_t)b0 * HH + TAIL_K + 3 * KCH, HH);
                    CP_COMMIT();
                }

                const uint32_t aBase = smb + (ch & 3) * STAGE_BYTES;
                const uint32_t wBase = aBase + A_BYTES;
#pragma unroll
                for (int ks = 0; ks < 4; ks++) {
                    uint32_t a0[4], a1[4], bA[4], bB[4];
                    ldsm4(a0, aBase + aoff0 + ks * 32);
                    ldsm4(a1, aBase + aoff1 + ks * 32);
                    ldsm4(bA, wBase + boffA + ks * 32);
                    ldsm4(bB, wBase + boffB + ks * 32);
                    mma16(acc[0][0], a0, bA[0], bA[1]);
                    mma16(acc[1][0], a1, bA[0], bA[1]);
                    mma16(acc[0][1], a0, bA[2], bA[3]);
                    mma16(acc[1][1], a1, bA[2], bA[3]);
                    mma16(acc[0][2], a0, bB[0], bB[1]);
                    mma16(acc[1][2], a1, bB[0], bB[1]);
                    mma16(acc[0][3], a0, bB[2], bB[3]);
                    mma16(acc[1][3], a1, bB[2], bB[3]);
                }
            }

            // publish partial for tile d
            {
                float4* pp = (float4*)(g_part + (size_t)d * 8192) + tid * 8;
                const float* af = &acc[0][0][0];
#pragma unroll
                for (int i = 0; i < 8; i++)
                    pp[i] = make_float4(af[4 * i], af[4 * i + 1],
                                        af[4 * i + 2], af[4 * i + 3]);
            }
            __syncthreads();
            if (tid == 0) rel_add(&g_flagp[s * 128 + d]);
        }
    }
}

__global__ __launch_bounds__(256, 2) void lstm_persistent(
    const float* __restrict__ bih0, const float* __restrict__ bhh0,
    const float* __restrict__ bih1, const float* __restrict__ bhh1) {
    extern __shared__ char smraw[];
    __shared__ float bias_s[128];
    if (blockIdx.x < 128)
        lstm_run<HH, 1>(blockIdx.x, smraw, bias_s, bih1, bhh1);
    else if (blockIdx.x < 148)
        helper_run(blockIdx.x - 128, smraw);
    else
        lstm_run<FF, 0>(blockIdx.x - 148, smraw, bias_s, bih0, bhh0);
}

// ---------------- head + output packing ----------------
__global__ void linear_kernel(const float* __restrict__ W_lin,
                              const float* __restrict__ b_lin,
                              float* __restrict__ y) {
    __shared__ float hrow[HH];
    const int b = blockIdx.x;
    for (int i = threadIdx.x; i < HH; i += blockDim.x)
        hrow[i] = g_h1first[(size_t)b * HH + i];
    __syncthreads();
    const int f = threadIdx.x;
    float acc = b_lin[f];
    const float* wv = &W_lin[(size_t)f * HH];
#pragma unroll 4
    for (int k = 0; k < HH; k++) acc += hrow[k] * wv[k];
    y[(size_t)b * FF + f] = acc;
}

__global__ void write_states_kernel(float* __restrict__ out) {
    int i = blockIdx.x * blockDim.x + threadIdx.x;
    if (i >= BB * HH) return;
    const int YO = BB * FF;
    out[YO + i]               = g_h0fin[i];
    out[YO + BB * HH + i]     = g_h1fin[i];
    out[YO + 2 * BB * HH + i] = g_c0fin[i];
    out[YO + 3 * BB * HH + i] = g_c1fin[i];
}

extern "C" void kernel_launch(void* const* d_in, const int* in_sizes, int n_in,
                              void* d_out, int out_size) {
    (void)in_sizes; (void)n_in; (void)out_size;
    const float* x     = (const float*)d_in[0];
    const float* W_ih0 = (const float*)d_in[1];
    const float* W_hh0 = (const float*)d_in[2];
    const float* b_ih0 = (const float*)d_in[3];
    const float* b_hh0 = (const float*)d_in[4];
    const float* W_ih1 = (const float*)d_in[5];
    const float* W_hh1 = (const float*)d_in[6];
    const float* b_ih1 = (const float*)d_in[7];
    const float* b_hh1 = (const float*)d_in[8];
    const float* W_lin = (const float*)d_in[9];
    const float* b_lin = (const float*)d_in[10];
    float* out = (float*)d_out;

    cudaFuncSetAttribute(lstm_persistent,
                         cudaFuncAttributeMaxDynamicSharedMemorySize, SMEM_BYTES);

    prep_all<<<(PREP_TOTAL + 255) / 256, 256>>>(x, W_ih0, W_hh0, W_ih1, W_hh1);
    lstm_persistent<<<276, 256, SMEM_BYTES>>>(b_ih0, b_hh0, b_ih1, b_hh1);
    linear_kernel<<<BB, FF>>>(W_lin, b_lin, out);
    write_states_kernel<<<(BB * HH + 255) / 256, 256>>>(out);
}

// round 11
// speedup vs baseline: 1.4258x; 1.2375x over previous
#include <cuda_runtime.h>
#include <cuda_fp16.h>
#include <math.h>
#include <stdint.h>

// ---------------- problem constants ----------------
#define TT 256
#define BB 256
#define FF 128
#define HH 1024

// ---------------- tiling ----------------
#define KCH     64                         // K halves per chunk
#define ROWB    144                        // 72 halves per row
#define A_BYTES (64 * ROWB)                // 9216
#define W_BYTES (128 * ROWB)               // 18432
#define STAGE_BYTES (A_BYTES + W_BYTES)    // 27648
#define SMEM_BYTES  (4 * STAGE_BYTES)      // 110592

#define TAILC   2                          // L1 K-chunks offloaded to helpers
#define TAIL_K  (HH - TAILC * KCH)         // h1 col offset 896

// ---------------- persistent device state ----------------
__device__ __half g_h0h[3][BB * HH];       // triple-buffered h0
__device__ __half g_h1h[2][BB * HH];
__device__ __half g_xh[TT * BB * FF];
__device__ __half g_Wih0h[4 * HH * FF];
__device__ __half g_Whh0h[4 * HH * HH];
__device__ __half g_Wih1h[4 * HH * HH];
__device__ __half g_Whh1h[4 * HH * HH];
__device__ float  g_h0fin[BB * HH];
__device__ float  g_h1fin[BB * HH];
__device__ float  g_c0fin[BB * HH];
__device__ float  g_c1fin[BB * HH];
__device__ float  g_h1first[BB * HH];
__device__ float  g_part[128 * 64 * 128];  // per-L1-tile K-tail partials (32 f32/thread)
__device__ uint32_t g_flag0[TT * 4];       // layer0 step done (per m group)
__device__ uint32_t g_flag1[TT * 4];       // layer1 step done
__device__ uint32_t g_cons[TT * 4];        // layer1 consumed h0(s+1)
__device__ uint32_t g_flagp[TT * 128];     // helper partial ready (per L1 tile)

// ---------------- helpers ----------------
__device__ __forceinline__ uint32_t s2u(const void* p) {
    uint32_t a;
    asm("{ .reg .u64 t; cvta.to.shared.u64 t, %1; cvt.u32.u64 %0, t; }"
        : "=r"(a) : "l"(p));
    return a;
}

__device__ __forceinline__ void cp16(uint32_t s, const void* g) {
    asm volatile("cp.async.cg.shared.global [%0], [%1], 16;" :: "r"(s), "l"(g));
}
#define CP_COMMIT() asm volatile("cp.async.commit_group;" ::: "memory")
#define CP_WAIT(N)  asm volatile("cp.async.wait_group %0;" :: "n"(N) : "memory")

__device__ __forceinline__ void ldsm4(uint32_t* r, uint32_t addr) {
    asm volatile("ldmatrix.sync.aligned.m8n8.x4.shared.b16 {%0,%1,%2,%3}, [%4];"
        : "=r"(r[0]), "=r"(r[1]), "=r"(r[2]), "=r"(r[3]) : "r"(addr));
}

__device__ __forceinline__ void mma16(float* c, const uint32_t* a, uint32_t b0, uint32_t b1) {
    asm volatile(
        "mma.sync.aligned.m16n8k16.row.col.f32.f16.f16.f32 "
        "{%0,%1,%2,%3}, {%4,%5,%6,%7}, {%8,%9}, {%0,%1,%2,%3};"
        : "+f"(c[0]), "+f"(c[1]), "+f"(c[2]), "+f"(c[3])
        : "r"(a[0]), "r"(a[1]), "r"(a[2]), "r"(a[3]), "r"(b0), "r"(b1));
}

__device__ __forceinline__ void spin_ge(const uint32_t* p, uint32_t tgt) {
    uint32_t v;
    while (true) {
        asm volatile("ld.acquire.gpu.global.u32 %0, [%1];" : "=r"(v) : "l"(p) : "memory");
        if (v >= tgt) break;
        __nanosleep(32);
    }
}

__device__ __forceinline__ void rel_add(uint32_t* p) {
    asm volatile("red.release.gpu.global.add.u32 [%0], 1;" :: "l"(p) : "memory");
}

__device__ __forceinline__ float sigmoidf_(float x) { return 1.0f / (1.0f + expf(-x)); }

// ---------------- one-shot prep: fp16 conversions + state/flag zeroing ----------------
#define N_X   (TT * BB * FF)
#define N_WI0 (4 * HH * FF)
#define N_WHH (4 * HH * HH)
#define N_Z   (BB * HH)
#define PREP_TOTAL (N_X + N_WI0 + 3 * N_WHH + 2 * N_Z + 3 * TT * 4 + TT * 128)

__global__ void prep_all(const float* __restrict__ x,
                         const float* __restrict__ wi0, const float* __restrict__ wh0,
                         const float* __restrict__ wi1, const float* __restrict__ wh1) {
    long long i = (long long)blockIdx.x * blockDim.x + threadIdx.x;
    if (i >= PREP_TOTAL) return;
    if (i < N_X) { g_xh[i] = __float2half_rn(x[i]); return; }
    i -= N_X;
    if (i < N_WI0) { g_Wih0h[i] = __float2half_rn(wi0[i]); return; }
    i -= N_WI0;
    if (i < N_WHH) { g_Whh0h[i] = __float2half_rn(wh0[i]); return; }
    i -= N_WHH;
    if (i < N_WHH) { g_Wih1h[i] = __float2half_rn(wi1[i]); return; }
    i -= N_WHH;
    if (i < N_WHH) { g_Whh1h[i] = __float2half_rn(wh1[i]); return; }
    i -= N_WHH;
    if (i < N_Z) { g_h0h[0][i] = __float2half(0.0f); return; }
    i -= N_Z;
    if (i < N_Z) { g_h1h[0][i] = __float2half(0.0f); return; }
    i -= N_Z;
    if (i < TT * 4) { g_flag0[i] = 0; return; }
    i -= TT * 4;
    if (i < TT * 4) { g_flag1[i] = 0; return; }
    i -= TT * 4;
    if (i < TT * 4) { g_cons[i] = 0; return; }
    i -= TT * 4;
    g_flagp[i] = 0;
}

// ---------------- split chunk loaders (256 threads) ----------------
__device__ __forceinline__ void loadA(uint32_t dstA, int tid,
                                      const __half* __restrict__ aSrc, int ald) {
#pragma unroll
    for (int i = 0; i < 2; i++) {            // 64 rows x 8 segs
        int q = tid + i * 256;
        int row = q >> 3, seg = q & 7;
        cp16(dstA + row * ROWB + seg * 16, aSrc + (size_t)row * ald + seg * 8);
    }
}

__device__ __forceinline__ void loadW(uint32_t dstW, int tid,
                                      const __half* __restrict__ wSrc, int wld, int j0) {
#pragma unroll
    for (int i = 0; i < 4; i++) {            // 128 rows x 8 segs
        int q = tid + i * 256;
        int row = q >> 3, seg = q & 7;
        int g = row >> 5, u = row & 31;
        cp16(dstW + row * ROWB + seg * 16,
             wSrc + (size_t)(g * HH + j0 + u) * wld + seg * 8);
    }
}

// ---------------- persistent LSTM CTA (R8 structure; L1 drops TAILC tail chunks) ----------------
template <int K_IN, int LAYER>
__device__ __forceinline__ void lstm_run(int bid, char* smraw, float* bias_s,
                                         const float* __restrict__ b_ih,
                                         const float* __restrict__ b_hh) {
    constexpr int NC    = (K_IN + HH) / KCH;
    constexpr int SPLIT = K_IN / KCH;
    constexpr int NCE   = LAYER ? (NC - TAILC) : NC;   // L1: 30, L0: 18

    const int tid  = threadIdx.x;
    const int w    = tid >> 5;
    const int lane = tid & 31;
    const int wm   = w & 1;
    const int wn   = w >> 1;
    const int r4   = lane >> 2, cl = lane & 3;
    const int m    = bid & 3;
    const int nt   = bid >> 2;
    const int b0   = m * 64;
    const int j0   = nt * 32;

    const uint32_t smb = s2u(smraw);
    const __half* Wih = LAYER ? g_Wih1h : g_Wih0h;
    const __half* Whh = LAYER ? g_Whh1h : g_Whh0h;

    if (tid < 128) {
        int g = tid >> 5, u = tid & 31;
        bias_s[tid] = b_ih[g * HH + j0 + u] + b_hh[g * HH + j0 + u];
    }
    __syncthreads();

    const int arow = (lane & 7) + ((lane >> 3) & 1) * 8;
    const int aseg = (lane >> 4) & 1;
    const uint32_t aoff0 = (uint32_t)((wm * 32 + arow) * ROWB + aseg * 16);
    const uint32_t aoff1 = (uint32_t)((wm * 32 + 16 + arow) * ROWB + aseg * 16);
    const uint32_t boffA = (uint32_t)((((lane >> 4) & 1) * 32 + wn * 8 + (lane & 7)) * ROWB
                                      + ((lane >> 3) & 1) * 16);
    const uint32_t boffB = boffA + 64u * ROWB;

    float c_reg[2][2][2];
#pragma unroll
    for (int a = 0; a < 2; a++)
#pragma unroll
        for (int b = 0; b < 2; b++)
#pragma unroll
            for (int d = 0; d < 2; d++) c_reg[a][b][d] = 0.0f;

#pragma unroll 1
    for (int s = 0; s < TT; s++) {
        const __half* inP = LAYER ? g_h0h[(s + 1) % 3]
                                  : g_xh + (size_t)s * BB * FF;
        const __half* hP  = LAYER ? g_h1h[s & 1] : g_h0h[s % 3];

        auto wsrc_for = [&](int ch, const __half*& ws, int& wld) {
            if (ch < SPLIT) { ws = Wih + ch * KCH; wld = K_IN; }
            else            { ws = Whh + (ch - SPLIT) * KCH; wld = HH; }
        };
        auto asrc_for = [&](int ch, const __half*& as, int& ald) {
            if (ch < SPLIT) { as = inP + (size_t)b0 * K_IN + ch * KCH; ald = K_IN; }
            else            { as = hP + (size_t)b0 * HH + (ch - SPLIT) * KCH; ald = HH; }
        };

        // ---- prologue: flag-independent W (and x) loads BEFORE spins ----
#pragma unroll
        for (int st = 0; st < 3; st++) {
            const __half* ws; int wld;
            wsrc_for(st, ws, wld);
            loadW(smb + st * STAGE_BYTES + A_BYTES, tid, ws, wld, j0);
        }

        if (LAYER == 0) {
            const __half* as; int ald;
            asrc_for(0, as, ald);
            loadA(smb + 0 * STAGE_BYTES, tid, as, ald);
            CP_COMMIT();
            asrc_for(1, as, ald);
            loadA(smb + 1 * STAGE_BYTES, tid, as, ald);
            CP_COMMIT();
            if (s > 0) {
                if (tid == 0) spin_ge(&g_flag0[(s - 1) * 4 + m], 32);
                __syncthreads();
            }
            asrc_for(2, as, ald);
            loadA(smb + 2 * STAGE_BYTES, tid, as, ald);
            CP_COMMIT();
        } else {
            if (tid == 0) spin_ge(&g_flag0[s * 4 + m], 32);
            __syncthreads();
#pragma unroll
            for (int st = 0; st < 3; st++) {
                const __half* as; int ald;
                asrc_for(st, as, ald);
                loadA(smb + st * STAGE_BYTES, tid, as, ald);
                CP_COMMIT();
            }
        }

        float acc[2][4][4];
#pragma unroll
        for (int mi = 0; mi < 2; mi++)
#pragma unroll
            for (int g = 0; g < 4; g++)
#pragma unroll
                for (int q = 0; q < 4; q++) acc[mi][g][q] = 0.0f;

#pragma unroll 1
        for (int ch = 0; ch < NCE; ch++) {
            if (ch >= NCE - 1)      { CP_WAIT(0); }
            else if (ch == NCE - 2) { CP_WAIT(1); }
            else                    { CP_WAIT(2); }
            __syncthreads();

            if (ch + 3 < NCE) {
                int buf = (ch + 3) & 3;
                const __half* ws; int wld;
                wsrc_for(ch + 3, ws, wld);
                loadW(smb + buf * STAGE_BYTES + A_BYTES, tid, ws, wld, j0);

                if (LAYER == 1 && s > 0 && ch == SPLIT - 3) {
                    if (tid == 0) spin_ge(&g_flag1[(s - 1) * 4 + m], 32);
                    __syncthreads();
                }

                const __half* as; int ald;
                asrc_for(ch + 3, as, ald);
                loadA(smb + buf * STAGE_BYTES, tid, as, ald);
                CP_COMMIT();
            }

            const uint32_t aBase = smb + (ch & 3) * STAGE_BYTES;
            const uint32_t wBase = aBase + A_BYTES;

#pragma unroll
            for (int ks = 0; ks < 4; ks++) {
                uint32_t a0[4], a1[4], bA[4], bB[4];
                ldsm4(a0, aBase + aoff0 + ks * 32);
                ldsm4(a1, aBase + aoff1 + ks * 32);
                ldsm4(bA, wBase + boffA + ks * 32);
                ldsm4(bB, wBase + boffB + ks * 32);
                mma16(acc[0][0], a0, bA[0], bA[1]);
                mma16(acc[1][0], a1, bA[0], bA[1]);
                mma16(acc[0][1], a0, bA[2], bA[3]);
                mma16(acc[1][1], a1, bA[2], bA[3]);
                mma16(acc[0][2], a0, bB[0], bB[1]);
                mma16(acc[1][2], a1, bB[0], bB[1]);
                mma16(acc[0][3], a0, bB[2], bB[3]);
                mma16(acc[1][3], a1, bB[2], bB[3]);
            }
        }

        __syncthreads();
        // layer1: signal h0(s+1) fully consumed
        if (LAYER == 1 && tid == 0) rel_add(&g_cons[s * 4 + m]);

        // layer1: fold in the helper's K-tail partial before the gate math
        if (LAYER == 1) {
            if (tid == 0) spin_ge(&g_flagp[s * 128 + bid], 1);
            __syncthreads();
            const float4* pp = (const float4*)(g_part + (size_t)bid * 8192) + tid * 8;
            float* af = &acc[0][0][0];
#pragma unroll
            for (int i = 0; i < 8; i++) {
                float4 v = pp[i];
                af[4 * i + 0] += v.x; af[4 * i + 1] += v.y;
                af[4 * i + 2] += v.z; af[4 * i + 3] += v.w;
            }
        }

        // ---- epilogue: compute gates first (before any WAR spin) ----
        float hv_all[2][2][2];
#pragma unroll
        for (int mi = 0; mi < 2; mi++)
#pragma unroll
            for (int rh = 0; rh < 2; rh++)
#pragma unroll
                for (int du = 0; du < 2; du++) {
                    const int q = rh * 2 + du;
                    const int ul = wn * 8 + 2 * cl + du;
                    float iv = acc[mi][0][q] + bias_s[ul];
                    float fv = acc[mi][1][q] + bias_s[32 + ul];
                    float gv = acc[mi][2][q] + bias_s[64 + ul];
                    float ov = acc[mi][3][q] + bias_s[96 + ul];
                    float cn = sigmoidf_(fv) * c_reg[mi][rh][du]
                             + sigmoidf_(iv) * tanhf(gv);
                    c_reg[mi][rh][du] = cn;
                    hv_all[mi][rh][du] = sigmoidf_(ov) * tanhf(cn);
                }

        // layer0 WAR: before overwriting h0 slot (s+1)%3, wait for cons(s-3)
        if (LAYER == 0 && s >= 3) {
            if (tid == 0) spin_ge(&g_cons[(s - 3) * 4 + m], 32);
            __syncthreads();
        }

        __half* hOut = LAYER ? g_h1h[(s + 1) & 1] : g_h0h[(s + 1) % 3];
#pragma unroll
        for (int mi = 0; mi < 2; mi++)
#pragma unroll
            for (int rh = 0; rh < 2; rh++) {
                const int row = b0 + wm * 32 + mi * 16 + r4 + rh * 8;
                const int col = j0 + wn * 8 + 2 * cl;
                *(__half2*)&hOut[(size_t)row * HH + col] =
                    __floats2half2_rn(hv_all[mi][rh][0], hv_all[mi][rh][1]);
                if (LAYER == 1 && s == 0)
                    *(float2*)&g_h1first[(size_t)row * HH + col] =
                        make_float2(hv_all[mi][rh][0], hv_all[mi][rh][1]);
                if (s == TT - 1) {
                    float* hf = LAYER ? g_h1fin : g_h0fin;
                    float* cf = LAYER ? g_c1fin : g_c0fin;
                    *(float2*)&hf[(size_t)row * HH + col] =
                        make_float2(hv_all[mi][rh][0], hv_all[mi][rh][1]);
                    *(float2*)&cf[(size_t)row * HH + col] =
                        make_float2(c_reg[mi][rh][0], c_reg[mi][rh][1]);
                }
            }
        __syncthreads();
        if (tid == 0) rel_add(LAYER ? &g_flag1[s * 4 + m] : &g_flag0[s * 4 + m]);
    }
}

// ---------------- helper CTA: L1 K-tail partials (h1 cols [896,1024)) ----------------
// 40 helpers, each serving 3-4 L1 tiles; per-tile m-group gating, incremental publish.
__device__ void helper_run(int j, char* smraw) {
    const int tid  = threadIdx.x;
    const int w    = tid >> 5;
    const int lane = tid & 31;
    const int wm   = w & 1;
    const int wn   = w >> 1;
    const uint32_t smb = s2u(smraw);

    const int arow = (lane & 7) + ((lane >> 3) & 1) * 8;
    const int aseg = (lane >> 4) & 1;
    const uint32_t aoff0 = (uint32_t)((wm * 32 + arow) * ROWB + aseg * 16);
    const uint32_t aoff1 = (uint32_t)((wm * 32 + 16 + arow) * ROWB + aseg * 16);
    const uint32_t boffA = (uint32_t)((((lane >> 4) & 1) * 32 + wn * 8 + (lane & 7)) * ROWB
                                      + ((lane >> 3) & 1) * 16);
    const uint32_t boffB = boffA + 64u * ROWB;

    const int d0  = (j < 32) ? j * 3 : 96 + (j - 32) * 4;
    const int cnt = (j < 32) ? 3 : 4;

#pragma unroll 1
    for (int s = 0; s < TT; s++) {
        const __half* hB = g_h1h[s & 1];

#pragma unroll 1
        for (int k = 0; k < cnt; k++) {
            const int d  = d0 + k;
            const int m  = d & 3;
            const int b0 = m * 64;
            const int j0 = (d >> 2) * 32;

            // gate: h1(s) of group m ready (step s=0 uses the pre-zeroed buffer)
            if (s > 0) {
                if (tid == 0) spin_ge(&g_flag1[(s - 1) * 4 + m], 32);
                __syncthreads();
            }

            // load both tail chunks (2-stage mini pipeline)
#pragma unroll
            for (int st = 0; st < TAILC; st++) {
                loadW(smb + st * STAGE_BYTES + A_BYTES, tid,
                      g_Whh1h + TAIL_K + st * KCH, HH, j0);
                loadA(smb + st * STAGE_BYTES, tid,
                      hB + (size_t)b0 * HH + TAIL_K + st * KCH, HH);
                CP_COMMIT();
            }

            float acc[2][4][4];
#pragma unroll
            for (int mi = 0; mi < 2; mi++)
#pragma unroll
                for (int g = 0; g < 4; g++)
#pragma unroll
                    for (int q = 0; q < 4; q++) acc[mi][g][q] = 0.0f;

#pragma unroll
            for (int ch = 0; ch < TAILC; ch++) {
                if (ch == 0) { CP_WAIT(1); } else { CP_WAIT(0); }
                __syncthreads();

                const uint32_t aBase = smb + ch * STAGE_BYTES;
                const uint32_t wBase = aBase + A_BYTES;
#pragma unroll
                for (int ks = 0; ks < 4; ks++) {
                    uint32_t a0[4], a1[4], bA[4], bB[4];
                    ldsm4(a0, aBase + aoff0 + ks * 32);
                    ldsm4(a1, aBase + aoff1 + ks * 32);
                    ldsm4(bA, wBase + boffA + ks * 32);
                    ldsm4(bB, wBase + boffB + ks * 32);
                    mma16(acc[0][0], a0, bA[0], bA[1]);
                    mma16(acc[1][0], a1, bA[0], bA[1]);
                    mma16(acc[0][1], a0, bA[2], bA[3]);
                    mma16(acc[1][1], a1, bA[2], bA[3]);
                    mma16(acc[0][2], a0, bB[0], bB[1]);
                    mma16(acc[1][2], a1, bB[0], bB[1]);
                    mma16(acc[0][3], a0, bB[2], bB[3]);
                    mma16(acc[1][3], a1, bB[2], bB[3]);
                }
            }

            // publish partial for tile d (same thread<->acc layout as lstm_run)
            {
                float4* pp = (float4*)(g_part + (size_t)d * 8192) + tid * 8;
                const float* af = &acc[0][0][0];
#pragma unroll
                for (int i = 0; i < 8; i++)
                    pp[i] = make_float4(af[4 * i], af[4 * i + 1],
                                        af[4 * i + 2], af[4 * i + 3]);
            }
            __syncthreads();
            if (tid == 0) rel_add(&g_flagp[s * 128 + d]);
        }
    }
}

__global__ __launch_bounds__(256, 2) __cluster_dims__(2, 1, 1)
void lstm_persistent(
    const float* __restrict__ bih0, const float* __restrict__ bhh0,
    const float* __restrict__ bih1, const float* __restrict__ bhh1) {
    extern __shared__ char smraw[];
    __shared__ float bias_s[128];
    if (blockIdx.x < 128)
        lstm_run<HH, 1>(blockIdx.x, smraw, bias_s, bih1, bhh1);
    else if (blockIdx.x < 148)
        helper_run(blockIdx.x - 128, smraw);
    else if (blockIdx.x < 276)
        lstm_run<FF, 0>(blockIdx.x - 148, smraw, bias_s, bih0, bhh0);
    else
        helper_run(20 + (blockIdx.x - 276), smraw);
}

// ---------------- head + output packing ----------------
__global__ void linear_kernel(const float* __restrict__ W_lin,
                              const float* __restrict__ b_lin,
                              float* __restrict__ y) {
    __shared__ float hrow[HH];
    const int b = blockIdx.x;
    for (int i = threadIdx.x; i < HH; i += blockDim.x)
        hrow[i] = g_h1first[(size_t)b * HH + i];
    __syncthreads();
    const int f = threadIdx.x;
    float acc = b_lin[f];
    const float* wv = &W_lin[(size_t)f * HH];
#pragma unroll 4
    for (int k = 0; k < HH; k++) acc += hrow[k] * wv[k];
    y[(size_t)b * FF + f] = acc;
}

__global__ void write_states_kernel(float* __restrict__ out) {
    int i = blockIdx.x * blockDim.x + threadIdx.x;
    if (i >= BB * HH) return;
    const int YO = BB * FF;
    out[YO + i]               = g_h0fin[i];
    out[YO + BB * HH + i]     = g_h1fin[i];
    out[YO + 2 * BB * HH + i] = g_c0fin[i];
    out[YO + 3 * BB * HH + i] = g_c1fin[i];
}

extern "C" void kernel_launch(void* const* d_in, const int* in_sizes, int n_in,
                              void* d_out, int out_size) {
    (void)in_sizes; (void)n_in; (void)out_size;
    const float* x     = (const float*)d_in[0];
    const float* W_ih0 = (const float*)d_in[1];
    const float* W_hh0 = (const float*)d_in[2];
    const float* b_ih0 = (const float*)d_in[3];
    const float* b_hh0 = (const float*)d_in[4];
    const float* W_ih1 = (const float*)d_in[5];
    const float* W_hh1 = (const float*)d_in[6];
    const float* b_ih1 = (const float*)d_in[7];
    const float* b_hh1 = (const float*)d_in[8];
    const float* W_lin = (const float*)d_in[9];
    const float* b_lin = (const float*)d_in[10];
    float* out = (float*)d_out;

    cudaFuncSetAttribute(lstm_persistent,
                         cudaFuncAttributeMaxDynamicSharedMemorySize, SMEM_BYTES);

    prep_all<<<(PREP_TOTAL + 255) / 256, 256>>>(x, W_ih0, W_hh0, W_ih1, W_hh1);
    lstm_persistent<<<296, 256, SMEM_BYTES>>>(b_ih0, b_hh0, b_ih1, b_hh1);
    linear_kernel<<<BB, FF>>>(W_lin, b_lin, out);
    write_states_kernel<<<(BB * HH + 255) / 256, 256>>>(out);
}

// round 12
// speedup vs baseline: 1.4774x; 1.0362x over previous
#include <cuda_runtime.h>
#include <cuda_fp16.h>
#include <math.h>
#include <stdint.h>

// ---------------- problem constants ----------------
#define TT 256
#define BB 256
#define FF 128
#define HH 1024

// ---------------- tiling ----------------
#define KCH     64                         // K halves per chunk
#define ROWB    144                        // 72 halves per row
#define A_BYTES (64 * ROWB)                // 9216
#define W_BYTES (128 * ROWB)               // 18432
#define STAGE_BYTES (A_BYTES + W_BYTES)    // 27648
#define SMEM_BYTES  (4 * STAGE_BYTES)      // 110592

#define XRING   8                          // xproj ring depth (steps)

// ---------------- persistent device state ----------------
__device__ __half g_h0h[3][BB * HH];       // triple-buffered h0
__device__ __half g_h1h[2][BB * HH];
__device__ __half g_xh[TT * BB * FF];
__device__ __half g_Wih0h[4 * HH * FF];
__device__ __half g_Whh0h[4 * HH * HH];
__device__ __half g_Wih1h[4 * HH * HH];
__device__ __half g_Whh1h[4 * HH * HH];
__device__ float  g_h0fin[BB * HH];
__device__ float  g_h1fin[BB * HH];
__device__ float  g_c0fin[BB * HH];
__device__ float  g_c1fin[BB * HH];
__device__ float  g_h1first[BB * HH];
__device__ float  g_xproj[XRING * BB * 4 * HH];  // 32 MB fp32 x-projection ring
__device__ uint32_t g_flag0[TT * 4];       // layer0 step done (per m group)
__device__ uint32_t g_flag1[TT * 4];       // layer1 step done
__device__ uint32_t g_cons[TT * 4];        // layer1 consumed h0(s+1)
__device__ uint32_t g_flagx[TT * 128];     // xproj tile ready (per L0 tile)
__device__ uint32_t g_xcons[TT * 128];     // L0 consumed xproj tile (ring WAR)

// ---------------- helpers ----------------
__device__ __forceinline__ uint32_t s2u(const void* p) {
    uint32_t a;
    asm("{ .reg .u64 t; cvta.to.shared.u64 t, %1; cvt.u32.u64 %0, t; }"
        : "=r"(a) : "l"(p));
    return a;
}

__device__ __forceinline__ void cp16(uint32_t s, const void* g) {
    asm volatile("cp.async.cg.shared.global [%0], [%1], 16;" :: "r"(s), "l"(g));
}
#define CP_COMMIT() asm volatile("cp.async.commit_group;" ::: "memory")
#define CP_WAIT(N)  asm volatile("cp.async.wait_group %0;" :: "n"(N) : "memory")

__device__ __forceinline__ void ldsm4(uint32_t* r, uint32_t addr) {
    asm volatile("ldmatrix.sync.aligned.m8n8.x4.shared.b16 {%0,%1,%2,%3}, [%4];"
        : "=r"(r[0]), "=r"(r[1]), "=r"(r[2]), "=r"(r[3]) : "r"(addr));
}

__device__ __forceinline__ void mma16(float* c, const uint32_t* a, uint32_t b0, uint32_t b1) {
    asm volatile(
        "mma.sync.aligned.m16n8k16.row.col.f32.f16.f16.f32 "
        "{%0,%1,%2,%3}, {%4,%5,%6,%7}, {%8,%9}, {%0,%1,%2,%3};"
        : "+f"(c[0]), "+f"(c[1]), "+f"(c[2]), "+f"(c[3])
        : "r"(a[0]), "r"(a[1]), "r"(a[2]), "r"(a[3]), "r"(b0), "r"(b1));
}

__device__ __forceinline__ void spin_ge(const uint32_t* p, uint32_t tgt) {
    uint32_t v;
    while (true) {
        asm volatile("ld.acquire.gpu.global.u32 %0, [%1];" : "=r"(v) : "l"(p) : "memory");
        if (v >= tgt) break;
        __nanosleep(32);
    }
}

__device__ __forceinline__ void rel_add(uint32_t* p) {
    asm volatile("red.release.gpu.global.add.u32 [%0], 1;" :: "l"(p) : "memory");
}

__device__ __forceinline__ float sigmoidf_(float x) { return 1.0f / (1.0f + expf(-x)); }

// ---------------- one-shot prep: fp16 conversions + state/flag zeroing ----------------
#define N_X   (TT * BB * FF)
#define N_WI0 (4 * HH * FF)
#define N_WHH (4 * HH * HH)
#define N_Z   (BB * HH)
#define PREP_TOTAL (N_X + N_WI0 + 3 * N_WHH + 2 * N_Z + 3 * TT * 4 + 2 * TT * 128)

__global__ void prep_all(const float* __restrict__ x,
                         const float* __restrict__ wi0, const float* __restrict__ wh0,
                         const float* __restrict__ wi1, const float* __restrict__ wh1) {
    long long i = (long long)blockIdx.x * blockDim.x + threadIdx.x;
    if (i >= PREP_TOTAL) return;
    if (i < N_X) { g_xh[i] = __float2half_rn(x[i]); return; }
    i -= N_X;
    if (i < N_WI0) { g_Wih0h[i] = __float2half_rn(wi0[i]); return; }
    i -= N_WI0;
    if (i < N_WHH) { g_Whh0h[i] = __float2half_rn(wh0[i]); return; }
    i -= N_WHH;
    if (i < N_WHH) { g_Wih1h[i] = __float2half_rn(wi1[i]); return; }
    i -= N_WHH;
    if (i < N_WHH) { g_Whh1h[i] = __float2half_rn(wh1[i]); return; }
    i -= N_WHH;
    if (i < N_Z) { g_h0h[0][i] = __float2half(0.0f); return; }
    i -= N_Z;
    if (i < N_Z) { g_h1h[0][i] = __float2half(0.0f); return; }
    i -= N_Z;
    if (i < TT * 4) { g_flag0[i] = 0; return; }
    i -= TT * 4;
    if (i < TT * 4) { g_flag1[i] = 0; return; }
    i -= TT * 4;
    if (i < TT * 4) { g_cons[i] = 0; return; }
    i -= TT * 4;
    if (i < TT * 128) { g_flagx[i] = 0; return; }
    i -= TT * 128;
    g_xcons[i] = 0;
}

// ---------------- split chunk loaders (256 threads) ----------------
__device__ __forceinline__ void loadA(uint32_t dstA, int tid,
                                      const __half* __restrict__ aSrc, int ald) {
#pragma unroll
    for (int i = 0; i < 2; i++) {            // 64 rows x 8 segs
        int q = tid + i * 256;
        int row = q >> 3, seg = q & 7;
        cp16(dstA + row * ROWB + seg * 16, aSrc + (size_t)row * ald + seg * 8);
    }
}

__device__ __forceinline__ void loadW(uint32_t dstW, int tid,
                                      const __half* __restrict__ wSrc, int wld, int j0) {
#pragma unroll
    for (int i = 0; i < 4; i++) {            // 128 rows x 8 segs
        int q = tid + i * 256;
        int row = q >> 3, seg = q & 7;
        int g = row >> 5, u = row & 31;
        cp16(dstW + row * ROWB + seg * 16,
             wSrc + (size_t)(g * HH + j0 + u) * wld + seg * 8);
    }
}

// ---------------- persistent LSTM CTA ----------------
// LAYER 1: full K = 2048 (h0(s+1) then h1(s)), 32 chunks.
// LAYER 0: K = 1024 (h0(s) only, 16 chunks); x-projection comes precomputed
//          from helper CTAs via g_xproj and is folded in at the epilogue.
template <int LAYER>
__device__ __forceinline__ void lstm_run(int bid, char* smraw, float* bias_s,
                                         const float* __restrict__ b_ih,
                                         const float* __restrict__ b_hh) {
    constexpr int NC    = LAYER ? 32 : 16;
    constexpr int SPLIT = LAYER ? 16 : 0;

    const int tid  = threadIdx.x;
    const int w    = tid >> 5;
    const int lane = tid & 31;
    const int wm   = w & 1;
    const int wn   = w >> 1;
    const int r4   = lane >> 2, cl = lane & 3;
    const int m    = bid & 3;
    const int nt   = bid >> 2;
    const int b0   = m * 64;
    const int j0   = nt * 32;

    const uint32_t smb = s2u(smraw);
    const __half* Wih = LAYER ? g_Wih1h : g_Wih0h;   // Wih unused for LAYER 0
    const __half* Whh = LAYER ? g_Whh1h : g_Whh0h;

    if (tid < 128) {
        int g = tid >> 5, u = tid & 31;
        bias_s[tid] = b_ih[g * HH + j0 + u] + b_hh[g * HH + j0 + u];
    }
    __syncthreads();

    const int arow = (lane & 7) + ((lane >> 3) & 1) * 8;
    const int aseg = (lane >> 4) & 1;
    const uint32_t aoff0 = (uint32_t)((wm * 32 + arow) * ROWB + aseg * 16);
    const uint32_t aoff1 = (uint32_t)((wm * 32 + 16 + arow) * ROWB + aseg * 16);
    const uint32_t boffA = (uint32_t)((((lane >> 4) & 1) * 32 + wn * 8 + (lane & 7)) * ROWB
                                      + ((lane >> 3) & 1) * 16);
    const uint32_t boffB = boffA + 64u * ROWB;

    float c_reg[2][2][2];
#pragma unroll
    for (int a = 0; a < 2; a++)
#pragma unroll
        for (int b = 0; b < 2; b++)
#pragma unroll
            for (int d = 0; d < 2; d++) c_reg[a][b][d] = 0.0f;

#pragma unroll 1
    for (int s = 0; s < TT; s++) {
        const __half* inP = LAYER ? g_h0h[(s + 1) % 3] : nullptr;
        const __half* hP  = LAYER ? g_h1h[s & 1] : g_h0h[s % 3];

        auto wsrc_for = [&](int ch) {
            return (LAYER == 1 && ch < SPLIT) ? (Wih + ch * KCH)
                                              : (Whh + (ch - SPLIT) * KCH);
        };
        auto asrc_for = [&](int ch) {
            return (LAYER == 1 && ch < SPLIT)
                       ? (inP + (size_t)b0 * HH + ch * KCH)
                       : (hP + (size_t)b0 * HH + (ch - SPLIT) * KCH);
        };

        // ---- prologue: flag-independent W loads BEFORE the spin ----
#pragma unroll
        for (int st = 0; st < 3; st++)
            loadW(smb + st * STAGE_BYTES + A_BYTES, tid, wsrc_for(st), HH, j0);

        // gate the A loads: L1 needs h0(s+1); L0 needs h0(s)
        if (LAYER == 1) {
            if (tid == 0) spin_ge(&g_flag0[s * 4 + m], 32);
            __syncthreads();
        } else if (s > 0) {
            if (tid == 0) spin_ge(&g_flag0[(s - 1) * 4 + m], 32);
            __syncthreads();
        }
#pragma unroll
        for (int st = 0; st < 3; st++) {
            loadA(smb + st * STAGE_BYTES, tid, asrc_for(st), HH);
            CP_COMMIT();
        }

        float acc[2][4][4];
#pragma unroll
        for (int mi = 0; mi < 2; mi++)
#pragma unroll
            for (int g = 0; g < 4; g++)
#pragma unroll
                for (int q = 0; q < 4; q++) acc[mi][g][q] = 0.0f;

#pragma unroll 1
        for (int ch = 0; ch < NC; ch++) {
            if (ch >= NC - 1)      { CP_WAIT(0); }
            else if (ch == NC - 2) { CP_WAIT(1); }
            else                   { CP_WAIT(2); }
            __syncthreads();

            if (ch + 3 < NC) {
                int buf = (ch + 3) & 3;
                loadW(smb + buf * STAGE_BYTES + A_BYTES, tid, wsrc_for(ch + 3), HH, j0);

                if (LAYER == 1 && s > 0 && ch == SPLIT - 3) {
                    if (tid == 0) spin_ge(&g_flag1[(s - 1) * 4 + m], 32);
                    __syncthreads();
                }

                loadA(smb + buf * STAGE_BYTES, tid, asrc_for(ch + 3), HH);
                CP_COMMIT();
            }

            const uint32_t aBase = smb + (ch & 3) * STAGE_BYTES;
            const uint32_t wBase = aBase + A_BYTES;

#pragma unroll
            for (int ks = 0; ks < 4; ks++) {
                uint32_t a0[4], a1[4], bA[4], bB[4];
                ldsm4(a0, aBase + aoff0 + ks * 32);
                ldsm4(a1, aBase + aoff1 + ks * 32);
                ldsm4(bA, wBase + boffA + ks * 32);
                ldsm4(bB, wBase + boffB + ks * 32);
                mma16(acc[0][0], a0, bA[0], bA[1]);
                mma16(acc[1][0], a1, bA[0], bA[1]);
                mma16(acc[0][1], a0, bA[2], bA[3]);
                mma16(acc[1][1], a1, bA[2], bA[3]);
                mma16(acc[0][2], a0, bB[0], bB[1]);
                mma16(acc[1][2], a1, bB[0], bB[1]);
                mma16(acc[0][3], a0, bB[2], bB[3]);
                mma16(acc[1][3], a1, bB[2], bB[3]);
            }
        }

        __syncthreads();
        // layer1: signal h0(s+1) fully consumed
        if (LAYER == 1 && tid == 0) rel_add(&g_cons[s * 4 + m]);

        // layer0: fold in the precomputed x-projection tile (helpers run ~8
        // steps ahead, so this flag is essentially always already set)
        if (LAYER == 0) {
            if (tid == 0) spin_ge(&g_flagx[s * 128 + bid], 1);
            __syncthreads();
            const float* xp = g_xproj + (size_t)(s & (XRING - 1)) * BB * 4 * HH;
#pragma unroll
            for (int mi = 0; mi < 2; mi++)
#pragma unroll
                for (int rh = 0; rh < 2; rh++) {
                    const int row = b0 + wm * 32 + mi * 16 + r4 + rh * 8;
                    const int col = j0 + wn * 8 + 2 * cl;
#pragma unroll
                    for (int g = 0; g < 4; g++) {
                        float2 v = *(const float2*)&xp[(size_t)row * (4 * HH)
                                                       + g * HH + col];
                        acc[mi][g][rh * 2 + 0] += v.x;
                        acc[mi][g][rh * 2 + 1] += v.y;
                    }
                }
        }

        // ---- epilogue: compute gates first (before any WAR spin) ----
        float hv_all[2][2][2];
#pragma unroll
        for (int mi = 0; mi < 2; mi++)
#pragma unroll
            for (int rh = 0; rh < 2; rh++)
#pragma unroll
                for (int du = 0; du < 2; du++) {
                    const int q = rh * 2 + du;
                    const int ul = wn * 8 + 2 * cl + du;
                    float iv = acc[mi][0][q] + bias_s[ul];
                    float fv = acc[mi][1][q] + bias_s[32 + ul];
                    float gv = acc[mi][2][q] + bias_s[64 + ul];
                    float ov = acc[mi][3][q] + bias_s[96 + ul];
                    float cn = sigmoidf_(fv) * c_reg[mi][rh][du]
                             + sigmoidf_(iv) * tanhf(gv);
                    c_reg[mi][rh][du] = cn;
                    hv_all[mi][rh][du] = sigmoidf_(ov) * tanhf(cn);
                }

        // layer0 WAR: before overwriting h0 slot (s+1)%3, wait for cons(s-3)
        if (LAYER == 0 && s >= 3) {
            if (tid == 0) spin_ge(&g_cons[(s - 3) * 4 + m], 32);
            __syncthreads();
        }

        __half* hOut = LAYER ? g_h1h[(s + 1) & 1] : g_h0h[(s + 1) % 3];
#pragma unroll
        for (int mi = 0; mi < 2; mi++)
#pragma unroll
            for (int rh = 0; rh < 2; rh++) {
                const int row = b0 + wm * 32 + mi * 16 + r4 + rh * 8;
                const int col = j0 + wn * 8 + 2 * cl;
                *(__half2*)&hOut[(size_t)row * HH + col] =
                    __floats2half2_rn(hv_all[mi][rh][0], hv_all[mi][rh][1]);
                if (LAYER == 1 && s == 0)
                    *(float2*)&g_h1first[(size_t)row * HH + col] =
                        make_float2(hv_all[mi][rh][0], hv_all[mi][rh][1]);
                if (s == TT - 1) {
                    float* hf = LAYER ? g_h1fin : g_h0fin;
                    float* cf = LAYER ? g_c1fin : g_c0fin;
                    *(float2*)&hf[(size_t)row * HH + col] =
                        make_float2(hv_all[mi][rh][0], hv_all[mi][rh][1]);
                    *(float2*)&cf[(size_t)row * HH + col] =
                        make_float2(c_reg[mi][rh][0], c_reg[mi][rh][1]);
                }
            }
        __syncthreads();
        if (tid == 0) {
            rel_add(LAYER ? &g_flag1[s * 4 + m] : &g_flag0[s * 4 + m]);
            if (LAYER == 0) rel_add(&g_xcons[s * 128 + bid]);
        }
    }
}

// ---------------- helper CTA: precompute layer0 x-projection tiles ----------------
// 40 helpers; helper j serves tiles d = j + 40k. Pure feed-forward GEMM
// (x_t @ W_ih0^T), gated only by the 8-step ring WAR — no recurrence coupling.
__device__ void helper_run(int j, char* smraw) {
    const int tid  = threadIdx.x;
    const int w    = tid >> 5;
    const int lane = tid & 31;
    const int wm   = w & 1;
    const int wn   = w >> 1;
    const int r4   = lane >> 2, cl = lane & 3;
    const uint32_t smb = s2u(smraw);

    const int arow = (lane & 7) + ((lane >> 3) & 1) * 8;
    const int aseg = (lane >> 4) & 1;
    const uint32_t aoff0 = (uint32_t)((wm * 32 + arow) * ROWB + aseg * 16);
    const uint32_t aoff1 = (uint32_t)((wm * 32 + 16 + arow) * ROWB + aseg * 16);
    const uint32_t boffA = (uint32_t)((((lane >> 4) & 1) * 32 + wn * 8 + (lane & 7)) * ROWB
                                      + ((lane >> 3) & 1) * 16);
    const uint32_t boffB = boffA + 64u * ROWB;

    const int cnt = (j < 8) ? 4 : 3;   // tiles d = j, j+40, j+80 (, j+120)

#pragma unroll 1
    for (int t = 0; t < TT; t++) {
        float* xp = g_xproj + (size_t)(t & (XRING - 1)) * BB * 4 * HH;
        const __half* xB = g_xh + (size_t)t * BB * FF;

#pragma unroll 1
        for (int k = 0; k < cnt; k++) {
            const int d  = j + k * 40;
            const int b0 = (d & 3) * 64;
            const int j0 = (d >> 2) * 32;

            // ring WAR: slot t&7 was last used by step t-8
            if (t >= XRING) {
                if (tid == 0) spin_ge(&g_xcons[(t - XRING) * 128 + d], 1);
                __syncthreads();
            }

            // load both K-chunks of x and W_ih0 (K = 128 = 2 x 64)
#pragma unroll
            for (int st = 0; st < 2; st++) {
                loadW(smb + st * STAGE_BYTES + A_BYTES, tid,
                      g_Wih0h + st * KCH, FF, j0);
                loadA(smb + st * STAGE_BYTES, tid,
                      xB + (size_t)b0 * FF + st * KCH, FF);
                CP_COMMIT();
            }

            float acc[2][4][4];
#pragma unroll
            for (int mi = 0; mi < 2; mi++)
#pragma unroll
                for (int g = 0; g < 4; g++)
#pragma unroll
                    for (int q = 0; q < 4; q++) acc[mi][g][q] = 0.0f;

#pragma unroll
            for (int ch = 0; ch < 2; ch++) {
                if (ch == 0) { CP_WAIT(1); } else { CP_WAIT(0); }
                __syncthreads();

                const uint32_t aBase = smb + ch * STAGE_BYTES;
                const uint32_t wBase = aBase + A_BYTES;
#pragma unroll
                for (int ks = 0; ks < 4; ks++) {
                    uint32_t a0[4], a1[4], bA[4], bB[4];
                    ldsm4(a0, aBase + aoff0 + ks * 32);
                    ldsm4(a1, aBase + aoff1 + ks * 32);
                    ldsm4(bA, wBase + boffA + ks * 32);
                    ldsm4(bB, wBase + boffB + ks * 32);
                    mma16(acc[0][0], a0, bA[0], bA[1]);
                    mma16(acc[1][0], a1, bA[0], bA[1]);
                    mma16(acc[0][1], a0, bA[2], bA[3]);
                    mma16(acc[1][1], a1, bA[2], bA[3]);
                    mma16(acc[0][2], a0, bB[0], bB[1]);
                    mme_l:;
                    mma16(acc[1][2], a1, bB[0], bB[1]);
                    mma16(acc[0][3], a0, bB[2], bB[3]);
                    mma16(acc[1][3], a1, bB[2], bB[3]);
                }
            }

            // publish tile (same thread<->element layout the L0 epilogue reads)
#pragma unroll
            for (int mi = 0; mi < 2; mi++)
#pragma unroll
                for (int rh = 0; rh < 2; rh++) {
                    const int row = b0 + wm * 32 + mi * 16 + r4 + rh * 8;
                    const int col = j0 + wn * 8 + 2 * cl;
#pragma unroll
                    for (int g = 0; g < 4; g++)
                        *(float2*)&xp[(size_t)row * (4 * HH) + g * HH + col] =
                            make_float2(acc[mi][g][rh * 2 + 0],
                                        acc[mi][g][rh * 2 + 1]);
                }
            __syncthreads();
            if (tid == 0) rel_add(&g_flagx[t * 128 + d]);
        }
    }
}

__global__ __launch_bounds__(256, 2) void lstm_persistent(
    const float* __restrict__ bih0, const float* __restrict__ bhh0,
    const float* __restrict__ bih1, const float* __restrict__ bhh1) {
    extern __shared__ char smraw[];
    __shared__ float bias_s[128];
    if (blockIdx.x < 128)
        lstm_run<1>(blockIdx.x, smraw, bias_s, bih1, bhh1);
    else if (blockIdx.x < 256)
        lstm_run<0>(blockIdx.x - 128, smraw, bias_s, bih0, bhh0);
    else
        helper_run(blockIdx.x - 256, smraw);
}

// ---------------- head + output packing ----------------
__global__ void linear_kernel(const float* __restrict__ W_lin,
                              const float* __restrict__ b_lin,
                              float* __restrict__ y) {
    __shared__ float hrow[HH];
    const int b = blockIdx.x;
    for (int i = threadIdx.x; i < HH; i += blockDim.x)
        hrow[i] = g_h1first[(size_t)b * HH + i];
    __syncthreads();
    const int f = threadIdx.x;
    float acc = b_lin[f];
    const float* wv = &W_lin[(size_t)f * HH];
#pragma unroll 4
    for (int k = 0; k < HH; k++) acc += hrow[k] * wv[k];
    y[(size_t)b * FF + f] = acc;
}

__global__ void write_states_kernel(float* __restrict__ out) {
    int i = blockIdx.x * blockDim.x + threadIdx.x;
    if (i >= BB * HH) return;
    const int YO = BB * FF;
    out[YO + i]               = g_h0fin[i];
    out[YO + BB * HH + i]     = g_h1fin[i];
    out[YO + 2 * BB * HH + i] = g_c0fin[i];
    out[YO + 3 * BB * HH + i] = g_c1fin[i];
}

extern "C" void kernel_launch(void* const* d_in, const int* in_sizes, int n_in,
                              void* d_out, int out_size) {
    (void)in_sizes; (void)n_in; (void)out_size;
    const float* x     = (const float*)d_in[0];
    const float* W_ih0 = (const float*)d_in[1];
    const float* W_hh0 = (const float*)d_in[2];
    const float* b_ih0 = (const float*)d_in[3];
    const float* b_hh0 = (const float*)d_in[4];
    const float* W_ih1 = (const float*)d_in[5];
    const float* W_hh1 = (const float*)d_in[6];
    const float* b_ih1 = (const float*)d_in[7];
    const float* b_hh1 = (const float*)d_in[8];
    const float* W_lin = (const float*)d_in[9];
    const float* b_lin = (const float*)d_in[10];
    float* out = (float*)d_out;

    cudaFuncSetAttribute(lstm_persistent,
                         cudaFuncAttributeMaxDynamicSharedMemorySize, SMEM_BYTES);

    prep_all<<<(PREP_TOTAL + 255) / 256, 256>>>(x, W_ih0, W_hh0, W_ih1, W_hh1);
    lstm_persistent<<<296, 256, SMEM_BYTES>>>(b_ih0, b_hh0, b_ih1, b_hh1);
    linear_kernel<<<BB, FF>>>(W_lin, b_lin, out);
    write_states_kernel<<<(BB * HH + 255) / 256, 256>>>(out);
}